// round 7
// baseline (speedup 1.0000x reference)
#include <cuda_runtime.h>
#include <math.h>

#define NN  100000
#define EE  1600000
#define IND 512
#define HGD 64
#define OUTD 20

#define SCAN_BLK 1024
#define NBLK ((NN + SCAN_BLK - 1) / SCAN_BLK)   // 98

typedef unsigned long long ull;

// ---------------- scratch (static device globals; no allocs) ----------------
__device__ float g_deg[NN];               // deg, then dinv (in place)
__device__ int   g_cnt[NN];               // in-degree count
__device__ int   g_rowptr[NN + 1];        // CSR offsets (by dst)
__device__ int   g_cursor[NN];            // fill cursors
__device__ int   g_bsum[NBLK];            // scan block sums
__device__ int   g_csrc[EE];              // CSR: source node per edge
__device__ float g_cnrm[EE];              // CSR: norm per edge
__device__ __align__(16) float g_xw[(size_t)NN * HGD];
__device__ __align__(16) float g_h[(size_t)NN * HGD];

__device__ __forceinline__ float selu_f(float x) {
    const float a = 1.6732632423543772f, s = 1.0507009873554805f;
    return s * (x > 0.f ? x : a * expm1f(x));
}

// packed f32x2 helpers
__device__ __forceinline__ ull dup2(float x) {
    ull r;
    asm("mov.b64 %0, {%1, %1};" : "=l"(r) : "r"(__float_as_uint(x)));
    return r;
}
#define FMA2(d, a, b) asm("fma.rn.f32x2 %0, %1, %2, %0;" : "+l"(d) : "l"(a), "l"(b))
__device__ __forceinline__ void unpack2(ull v, float& lo, float& hi) {
    unsigned int l, h;
    asm("mov.b64 {%0, %1}, %2;" : "=r"(l), "=r"(h) : "l"(v));
    lo = __uint_as_float(l);
    hi = __uint_as_float(h);
}

// ---------------- degree + count ----------------
__global__ void k_deg_init() {
    int i = blockIdx.x * blockDim.x + threadIdx.x;
    if (i < NN) { g_deg[i] = 1.0f; g_cnt[i] = 0; }   // self-loop weight 1
}

__global__ void k_deg_acc(const int* __restrict__ ei, const float* __restrict__ w) {
    int e = blockIdx.x * blockDim.x + threadIdx.x;
    if (e < EE) {
        int c = ei[EE + e];
        atomicAdd(&g_deg[c], w[e]);
        atomicAdd(&g_cnt[c], 1);
    }
}

// ---------------- exclusive scan over g_cnt -> g_rowptr ----------------
__global__ void k_scan1() {
    __shared__ int sh[SCAN_BLK];
    int i = blockIdx.x * SCAN_BLK + threadIdx.x;
    int v = (i < NN) ? g_cnt[i] : 0;
    sh[threadIdx.x] = v;
    __syncthreads();
    for (int off = 1; off < SCAN_BLK; off <<= 1) {
        int t = (threadIdx.x >= off) ? sh[threadIdx.x - off] : 0;
        __syncthreads();
        sh[threadIdx.x] += t;
        __syncthreads();
    }
    if (i < NN) g_rowptr[i] = sh[threadIdx.x] - v;   // block-local exclusive
    if (threadIdx.x == SCAN_BLK - 1) g_bsum[blockIdx.x] = sh[threadIdx.x];
}

__global__ void k_scan_top() {
    __shared__ int sh[128];
    int t = threadIdx.x;
    int v = (t < NBLK) ? g_bsum[t] : 0;
    sh[t] = v;
    __syncthreads();
    for (int off = 1; off < 128; off <<= 1) {
        int u = (t >= off) ? sh[t - off] : 0;
        __syncthreads();
        sh[t] += u;
        __syncthreads();
    }
    if (t < NBLK) g_bsum[t] = sh[t] - v;   // exclusive
}

// also computes dinv (deg was final after k_deg_acc)
__global__ void k_scan_add() {
    int i = blockIdx.x * SCAN_BLK + threadIdx.x;
    if (i < NN) {
        int r = g_rowptr[i] + g_bsum[blockIdx.x];
        g_rowptr[i] = r;
        g_cursor[i] = r;
        float d = g_deg[i];
        g_deg[i] = d > 0.f ? rsqrtf(fmaxf(d, 1e-30f)) : 0.f;
    }
    if (i == 0) g_rowptr[NN] = EE;
}

// ---------------- CSR fill ----------------
__global__ void k_fill(const int* __restrict__ ei, const float* __restrict__ w) {
    int e = blockIdx.x * blockDim.x + threadIdx.x;
    if (e < EE) {
        int r = ei[e];
        int c = ei[EE + e];
        int pos = atomicAdd(&g_cursor[c], 1);
        g_csrc[pos] = r;
        g_cnrm[pos] = g_deg[r] * w[e] * g_deg[c];
    }
}

// ---------------- GEMM: C[M,64] = A[M,K] @ B[K,64], FFMA2 inner loop -------
// 128-row tiles, 256 threads, 8x4 micro-tile as 4 row-pairs x 4 cols.
__global__ void k_gemm128(const float* __restrict__ A, const float* __restrict__ B,
                          float* __restrict__ C, int M, int K) {
    __shared__ __align__(16) float As[16][128];  // [k][row]
    __shared__ __align__(16) float Bs[16][128];  // [k][2*col] duplicated
    int tid = threadIdx.x;
    int tx = tid & 15;             // col group (4 cols)
    int ty = tid >> 4;             // row group (8 rows = 4 pairs)
    int row0 = blockIdx.x * 128;

    ull acc[4][4];
#pragma unroll
    for (int i = 0; i < 4; i++)
#pragma unroll
        for (int j = 0; j < 4; j++) acc[i][j] = 0ull;

    for (int kt = 0; kt < K; kt += 16) {
        // A tile: 128 rows x 16 k, transpose-store
#pragma unroll
        for (int j = 0; j < 2; j++) {
            int f4 = tid * 2 + j;
            int r = f4 >> 2;
            int kq = (f4 & 3) * 4;
            int row = row0 + r;
            float4 v = (row < M) ? *(const float4*)&A[(size_t)row * K + kt + kq]
                                 : make_float4(0.f, 0.f, 0.f, 0.f);
            As[kq + 0][r] = v.x;
            As[kq + 1][r] = v.y;
            As[kq + 2][r] = v.z;
            As[kq + 3][r] = v.w;
        }
        // B tile, duplicated: Bs[k][2c] = Bs[k][2c+1] = B[k][c]
        {
            int bk = tid >> 4, bc = (tid & 15) * 4;
            float4 v = *(const float4*)&B[(size_t)(kt + bk) * 64 + bc];
            *(float4*)&Bs[bk][bc * 2]     = make_float4(v.x, v.x, v.y, v.y);
            *(float4*)&Bs[bk][bc * 2 + 4] = make_float4(v.z, v.z, v.w, v.w);
        }
        __syncthreads();
#pragma unroll
        for (int kk = 0; kk < 16; kk++) {
            const ull* ap = (const ull*)&As[kk][ty * 8];   // 4 row-pairs
            const ull* bp = (const ull*)&Bs[kk][tx * 8];   // 4 dup'd cols
            ull a0 = ap[0], a1 = ap[1], a2 = ap[2], a3 = ap[3];
            ull b0 = bp[0], b1 = bp[1], b2 = bp[2], b3 = bp[3];
            FMA2(acc[0][0], a0, b0); FMA2(acc[0][1], a0, b1);
            FMA2(acc[0][2], a0, b2); FMA2(acc[0][3], a0, b3);
            FMA2(acc[1][0], a1, b0); FMA2(acc[1][1], a1, b1);
            FMA2(acc[1][2], a1, b2); FMA2(acc[1][3], a1, b3);
            FMA2(acc[2][0], a2, b0); FMA2(acc[2][1], a2, b1);
            FMA2(acc[2][2], a2, b2); FMA2(acc[2][3], a2, b3);
            FMA2(acc[3][0], a3, b0); FMA2(acc[3][1], a3, b1);
            FMA2(acc[3][2], a3, b2); FMA2(acc[3][3], a3, b3);
        }
        __syncthreads();
    }
#pragma unroll
    for (int i = 0; i < 4; i++) {
        int r0 = row0 + ty * 8 + i * 2;
        float lo[4], hi[4];
#pragma unroll
        for (int j = 0; j < 4; j++) unpack2(acc[i][j], lo[j], hi[j]);
        if (r0 < M)
            *(float4*)&C[(size_t)r0 * 64 + tx * 4] = make_float4(lo[0], lo[1], lo[2], lo[3]);
        if (r0 + 1 < M)
            *(float4*)&C[(size_t)(r0 + 1) * 64 + tx * 4] = make_float4(hi[0], hi[1], hi[2], hi[3]);
    }
}

// ---------------- CSR gather + self-loop + bias + SELU -> g_h -------------
// 16 lanes per node; (src,norm) staged through smem; FFMA2 accumulate.
__global__ void k_gather(const float* __restrict__ bias) {
    __shared__ int   ssrc[16][32];
    __shared__ float snrm[16][32];
    int tid = threadIdx.x;
    int g = tid >> 4, lane = tid & 15;
    int n = blockIdx.x * 16 + g;
    if (n >= NN) return;                      // NN%16==0, uniform per block anyway
    int q = lane * 4;
    unsigned hm = 0xFFFFu << (tid & 16);      // half-warp mask

    float d = g_deg[n];
    float dd = d * d;
    float4 v = *(const float4*)&g_xw[(size_t)n * 64 + q];
    ull acc0 = 0, acc1 = 0;
    {
        ull dv = dup2(dd);
        const ull* vp = (const ull*)&v;
        FMA2(acc0, vp[0], dv);
        FMA2(acc1, vp[1], dv);
    }

    int s = g_rowptr[n], e2 = g_rowptr[n + 1];
    for (int base = s; base < e2; base += 32) {
        int cnt = e2 - base; if (cnt > 32) cnt = 32;
        if (lane < cnt)      { ssrc[g][lane]      = g_csrc[base + lane];
                               snrm[g][lane]      = g_cnrm[base + lane]; }
        if (lane + 16 < cnt) { ssrc[g][lane + 16] = g_csrc[base + lane + 16];
                               snrm[g][lane + 16] = g_cnrm[base + lane + 16]; }
        __syncwarp(hm);
        for (int j = 0; j < cnt; j++) {
            int s0 = ssrc[g][j];
            ull nd = dup2(snrm[g][j]);
            float4 u = *(const float4*)&g_xw[(size_t)s0 * 64 + q];
            const ull* up = (const ull*)&u;
            FMA2(acc0, up[0], nd);
            FMA2(acc1, up[1], nd);
        }
        __syncwarp(hm);
    }

    float4 b4 = *(const float4*)&bias[q];
    float ax, ay, az, aw;
    unpack2(acc0, ax, ay);
    unpack2(acc1, az, aw);
    float4 o;
    o.x = selu_f(ax + b4.x);
    o.y = selu_f(ay + b4.y);
    o.z = selu_f(az + b4.z);
    o.w = selu_f(aw + b4.w);
    *(float4*)&g_h[(size_t)n * 64 + q] = o;
}

// ---------------- fused dense MLP (3x 64x64 SELU + 64x20) + softmax --------
// 16 rows/block, 256 threads: j = tid&63 (col), rp = tid>>6 (4 rows = 2 pairs).
// Activations staged transposed: hsT[k][row], stride 20 (16B-aligned rows).
#define HST 20
__global__ void k_dense(const float* __restrict__ w0, const float* __restrict__ b0,
                        const float* __restrict__ w1, const float* __restrict__ b1,
                        const float* __restrict__ w2, const float* __restrict__ b2,
                        const float* __restrict__ w3, const float* __restrict__ b3,
                        float* __restrict__ out) {
    __shared__ float Ws[64][64];
    __shared__ __align__(16) float hsT[64][HST];
    __shared__ float lg[16][20];
    __shared__ float bs[64];

    int tid = threadIdx.x;
    int j = tid & 63, rp = tid >> 6;
    int row0 = blockIdx.x * 16;

    // load activations transposed: hsT[f][r]
    for (int i = tid; i < 16 * 64; i += 256) {
        int r = i >> 6, f = i & 63;
        int row = row0 + r;
        hsT[f][r] = (row < NN) ? g_h[(size_t)row * 64 + f] : 0.f;
    }

    const float* Wp[3] = {w0, w1, w2};
    const float* Bp[3] = {b0, b1, b2};

    for (int L = 0; L < 3; L++) {
        __syncthreads();
        for (int i = tid; i < 4096; i += 256) Ws[i >> 6][i & 63] = Wp[L][i];
        if (tid < 64) bs[tid] = Bp[L][tid];
        __syncthreads();
        ull acc0 = dup2(bs[j]), acc1 = acc0;
        for (int k = 0; k < 64; k++) {
            const ull* hp = (const ull*)&hsT[k][rp * 4];   // 2 row-pairs
            ull wd = dup2(Ws[k][j]);
            FMA2(acc0, hp[0], wd);
            FMA2(acc1, hp[1], wd);
        }
        float v0, v1, v2, v3;
        unpack2(acc0, v0, v1);
        unpack2(acc1, v2, v3);
        __syncthreads();
        hsT[j][rp * 4 + 0] = selu_f(v0);
        hsT[j][rp * 4 + 1] = selu_f(v1);
        hsT[j][rp * 4 + 2] = selu_f(v2);
        hsT[j][rp * 4 + 3] = selu_f(v3);
    }

    // final layer: 64 -> 20, then softmax
    __syncthreads();
    for (int i = tid; i < 64 * 20; i += 256) Ws[i / 20][i % 20] = w3[i];
    if (tid < 20) bs[tid] = b3[tid];
    __syncthreads();

    if (j < 20) {
        ull acc0 = dup2(bs[j]), acc1 = acc0;
        for (int k = 0; k < 64; k++) {
            const ull* hp = (const ull*)&hsT[k][rp * 4];
            ull wd = dup2(Ws[k][j]);
            FMA2(acc0, hp[0], wd);
            FMA2(acc1, hp[1], wd);
        }
        float v0, v1, v2, v3;
        unpack2(acc0, v0, v1);
        unpack2(acc1, v2, v3);
        lg[rp * 4 + 0][j] = v0;
        lg[rp * 4 + 1][j] = v1;
        lg[rp * 4 + 2][j] = v2;
        lg[rp * 4 + 3][j] = v3;
    }
    __syncthreads();

    for (int idx = tid; idx < 16 * 20; idx += 256) {
        int r = idx / 20, jj = idx % 20;
        int row = row0 + r;
        if (row < NN) {
            float mx = -1e30f;
#pragma unroll
            for (int k = 0; k < 20; k++) mx = fmaxf(mx, lg[r][k]);
            float s = 0.f;
#pragma unroll
            for (int k = 0; k < 20; k++) s += expf(lg[r][k] - mx);
            out[(size_t)row * 20 + jj] = expf(lg[r][jj] - mx) / s;
        }
    }
}

// ---------------- launch ----------------
extern "C" void kernel_launch(void* const* d_in, const int* in_sizes, int n_in,
                              void* d_out, int out_size) {
    const float* x    = (const float*)d_in[0];
    const int*   ei   = (const int*)d_in[1];      // int32 (JAX x64 disabled)
    const float* ea   = (const float*)d_in[2];
    const float* gc0w = (const float*)d_in[3];
    const float* gc0b = (const float*)d_in[4];
    const float* gc1w = (const float*)d_in[5];
    const float* gc1b = (const float*)d_in[6];
    const float* l0w  = (const float*)d_in[7];
    const float* l0b  = (const float*)d_in[8];
    const float* l1w  = (const float*)d_in[9];
    const float* l1b  = (const float*)d_in[10];
    const float* l2w  = (const float*)d_in[11];
    const float* l2b  = (const float*)d_in[12];
    const float* l3w  = (const float*)d_in[13];
    const float* l3b  = (const float*)d_in[14];
    float*       out  = (float*)d_out;

    float *xw, *h;
    cudaGetSymbolAddress((void**)&xw, g_xw);
    cudaGetSymbolAddress((void**)&h,  g_h);

    const int T = 256;

    // normalization + CSR build (reused by both convs)
    k_deg_init<<<(NN + T - 1) / T, T>>>();
    k_deg_acc<<<(EE + T - 1) / T, T>>>(ei, ea);
    k_scan1<<<NBLK, SCAN_BLK>>>();
    k_scan_top<<<1, 128>>>();
    k_scan_add<<<NBLK, SCAN_BLK>>>();
    k_fill<<<(EE + T - 1) / T, T>>>(ei, ea);

    // conv 0
    k_gemm128<<<(NN + 127) / 128, T>>>(x, gc0w, xw, NN, IND);
    k_gather<<<(NN + 15) / 16, T>>>(gc0b);

    // conv 1
    k_gemm128<<<(NN + 127) / 128, T>>>(h, gc1w, xw, NN, HGD);
    k_gather<<<(NN + 15) / 16, T>>>(gc1b);

    // dense stack + softmax
    k_dense<<<(NN + 15) / 16, T>>>(l0w, l0b, l1w, l1b, l2w, l2b, l3w, l3b, out);
}